// round 14
// baseline (speedup 1.0000x reference)
#include <cuda_runtime.h>
#include <math.h>
#include <stdint.h>

// ---------------- problem constants (IMG 800x1024, strides 8..128) ----------
#define NBATCH 16
#define NCLS   80
#define TOPN   300
#define KC     1504          // slot stride per image (1500 real candidates)
#define NREAL  1500
#define NWORDS 47            // ceil(1504/32)
#define POST   100
#define CAP    4096          // survivor cap per (level,batch) pair

__constant__ int c_HW[5]   = {12800, 3200, 800, 208, 56};
__constant__ int c_CHW[5]  = {1024000, 256000, 64000, 16640, 4480};
__constant__ int c_LOFF[5] = {0, 204800, 256000, 268800, 272128};
__constant__ int c_R[5]    = {40, 80, 300, 300, 300};
__constant__ int c_BPP[5]  = {250, 63, 16, 5, 2};
__constant__ int c_BOFF[5] = {0, 4000, 5008, 5264, 5344};
#define NBLOCKS_COLLECT 5376
#define SCTR_TOTAL 273024
#define SCTR_BLOCKS 1067     // ceil(273024/256)
#define NSAMPLE 208

// ---------------- device scratch (static, allocation-free) ------------------
__device__ float    g_sctr[SCTR_TOTAL];          // exact sigmoid(ctr)
__device__ float    g_L[SCTR_TOTAL];             // per-position logit threshold
__device__ unsigned g_histpart[NSAMPLE * 2048];  // per-sample-block partial hists
__device__ unsigned g_scnt[80];
__device__ unsigned long long g_surv[(size_t)80 * CAP];
__device__ float    g_cscore[NBATCH * KC];       // fully rewritten by select each run
__device__ float4   g_cbox4[NBATCH * KC];
__device__ int      g_clabel[NBATCH * KC];

struct InPtrs {
    const float* loc[5];
    const float* cls[5];
    const float* box[5];
    const float* ctr[5];
};

__device__ __forceinline__ unsigned fkey(float f) {
    unsigned b = __float_as_uint(f);
    return b ^ ((unsigned)((int)b >> 31) | 0x80000000u);
}
__device__ __forceinline__ float sigm(float x) { return 1.0f / (1.0f + expf(-x)); }

__device__ __forceinline__ float approx_rcp(float d) {
    float r = __int_as_float(0x7EF311C3 - __float_as_int(d));
    r = r * (2.0f - d * r);
    r = r * (2.0f - d * r);
    return r;
}
// MUFU-free approx sigmoid (sampling only), |rel err| <= ~0.25%
__device__ __forceinline__ float approx_sig(float cv) {
    float t = fminf(cv, 60.0f) * -1.44269504f;
    float fl = floorf(t);
    float f = t - fl;
    float p2 = fmaf(fmaf(0.33718944f, f, 0.65763628f), f, 1.0017247f);
    float z = p2 * __int_as_float(((int)fl + 127) << 23);
    return approx_rcp(1.0f + z);
}

__device__ __forceinline__ void map_block(int bid, int& l, int& b, int& chunk) {
    if (bid < 4000)      l = 0;
    else if (bid < 5008) l = 1;
    else if (bid < 5264) l = 2;
    else if (bid < 5344) l = 3;
    else                 l = 4;
    int rel = bid - c_BOFF[l];
    b = rel / c_BPP[l];
    chunk = rel % c_BPP[l];
}

// ---------------- kernel 1: sctr init + sampled histogram [R7/R8-proven] -----
__global__ __launch_bounds__(256) void k_prep(InPtrs P) {
    int bid = blockIdx.x;
    if (bid < SCTR_BLOCKS) {
        int i = bid * 256 + threadIdx.x;
        if (i < SCTR_TOTAL) {
            int l = (i < 204800) ? 0 : (i < 256000) ? 1 : (i < 268800) ? 2 : (i < 272128) ? 3 : 4;
            g_sctr[i] = sigm(P.ctr[l][i - c_LOFF[l]]);
        }
        return;
    }
    __shared__ unsigned hist[2048];
    for (int i = threadIdx.x; i < 2048; i += 256) hist[i] = 0;
    __syncthreads();
    int sid = bid - SCTR_BLOCKS;
    int l, b, sub, nsub, stride;
    if (sid < 128)      { l = 0; b = sid >> 3; sub = sid & 7; nsub = 8; stride = 32; }
    else if (sid < 160) { l = 1; b = (sid - 128) >> 1; sub = (sid - 128) & 1; nsub = 2; stride = 8; }
    else if (sid < 176) { l = 2; b = sid - 160; sub = 0; nsub = 1; stride = 1; }
    else if (sid < 192) { l = 3; b = sid - 176; sub = 0; nsub = 1; stride = 1; }
    else                { l = 4; b = sid - 192; sub = 0; nsub = 1; stride = 1; }
    int chw4 = c_CHW[l] >> 2;
    int per = chw4 / nsub;
    int hw = c_HW[l];
    const float4* cls4 = (const float4*)(P.cls[l]) + (size_t)b * chw4 + (size_t)sub * per;
    const float4* ctr4 = (const float4*)(P.ctr[l]) + (size_t)b * (hw >> 2);
    int base_e = sub * per * 4;
    for (int i4 = threadIdx.x * stride; i4 < per; i4 += 256 * stride) {
        float4 v = cls4[i4];
        int e = base_e + (i4 << 2);
        int pos0 = e % hw;
        float4 cc = ctr4[pos0 >> 2];
        float vv[4] = {v.x, v.y, v.z, v.w};
        float ss[4] = {approx_sig(cc.x), approx_sig(cc.y), approx_sig(cc.z), approx_sig(cc.w)};
        #pragma unroll
        for (int k = 0; k < 4; k++) {
            float cv = vv[k];
            if (cv < -2.945f) continue;
            float a = approx_sig(cv) * ss[k];
            atomicAdd(&hist[min(2047, (int)(a * 2048.0f))], 1u);
        }
    }
    __syncthreads();
    for (int i = threadIdx.x; i < 2048; i += 256)
        g_histpart[sid * 2048 + i] = hist[i];   // store -> no cross-replay zeroing
}

// ---------------- kernel 2: threshold -> per-position logit L [R7/R8-proven] -
__global__ __launch_bounds__(256) void k_threshL() {
    __shared__ unsigned sh[2048];
    __shared__ unsigned part[256];
    __shared__ float s_thr;
    int p = blockIdx.x, t = threadIdx.x;
    int l = p / 16, b = p % 16;
    if (t == 0) { s_thr = 0.0f; g_scnt[p] = 0; }
    unsigned R = (unsigned)c_R[l];
    int first, cnt;
    if (l == 0)      { first = b * 8;        cnt = 8; }
    else if (l == 1) { first = 128 + b * 2;  cnt = 2; }
    else             { first = 160 + (l - 2) * 16 + b; cnt = 1; }
    unsigned lsum = 0;
    for (int i = 0; i < 8; i++) {
        int bin = t * 8 + i;
        unsigned s = 0;
        for (int c = 0; c < cnt; c++) s += g_histpart[(first + c) * 2048 + bin];
        sh[bin] = s; lsum += s;
    }
    part[t] = lsum;
    __syncthreads();
    for (int off = 1; off < 256; off <<= 1) {
        unsigned o = (t + off < 256) ? part[t + off] : 0u;
        __syncthreads();
        part[t] += o;
        __syncthreads();
    }
    unsigned cum = (t < 255) ? part[t + 1] : 0u;
    for (int i = 7; i >= 0; i--) {
        int bidx = t * 8 + i;
        unsigned hv = sh[bidx];
        if (cum < R && cum + hv >= R)
            s_thr = (float)bidx * (1.0f / 2048.0f) * 0.985f;
        cum += hv;
    }
    __syncthreads();
    float thr = s_thr;
    int hw = c_HW[l];
    int base = c_LOFF[l] + b * hw;
    for (int i = t; i < hw; i += 256) {
        float sv = g_sctr[base + i];
        float L;
        if (thr <= 0.0f) L = -2.944f;
        else {
            float x = thr / sv;
            if (x >= 1.0f) L = 1e30f;
            else L = fmaxf(logf(x / (1.0f - x)) - 0.02f, -2.944f);
        }
        g_L[base + i] = L;
    }
}

// ---------------- kernel 3: full sweep [R6/R13-proven float4 body] -----------
template <int HW>
__device__ __forceinline__ void collect_body(const float4* cls4, const float4* Lv,
                                             const float* sctr, int start, int chw, int p) {
    int e4end = min(start + 4096, chw) >> 2;
    for (int e4 = (start >> 2) + threadIdx.x; e4 < e4end; e4 += 256) {
        float4 v = cls4[e4];
        int e = e4 << 2;
        int c0 = e / HW;
        int pos0 = e - c0 * HW;
        float4 L4 = Lv[pos0 >> 2];
        float vv[4] = {v.x, v.y, v.z, v.w};
        float LL[4] = {L4.x, L4.y, L4.z, L4.w};
        #pragma unroll
        for (int k = 0; k < 4; k++) {
            float cv = vv[k];
            if (cv < LL[k]) continue;
            float se = sigm(cv);              // exact path, rare
            if (se <= 0.05f) continue;
            float sv = sctr[pos0 + k];
            float m = se * sv;
            unsigned key32 = __float_as_uint(m) | 0x80000000u;
            unsigned idx = (unsigned)((pos0 + k) * NCLS + c0);
            unsigned long long key = ((unsigned long long)key32 << 32) | (unsigned)(~idx);
            unsigned slot = atomicAdd(&g_scnt[p], 1u);
            if (slot < CAP) g_surv[(size_t)p * CAP + slot] = key;
        }
    }
}

__global__ __launch_bounds__(256) void k_collect(InPtrs P) {
    int l, b, chunk; map_block(blockIdx.x, l, b, chunk);
    int p = l * 16 + b;
    int start = chunk * 4096;
    switch (l) {
    case 0: collect_body<12800>((const float4*)(P.cls[0] + (size_t)b * 1024000),
            (const float4*)(g_L + 0 + b * 12800), g_sctr + 0 + b * 12800, start, 1024000, p); break;
    case 1: collect_body<3200>((const float4*)(P.cls[1] + (size_t)b * 256000),
            (const float4*)(g_L + 204800 + b * 3200), g_sctr + 204800 + b * 3200, start, 256000, p); break;
    case 2: collect_body<800>((const float4*)(P.cls[2] + (size_t)b * 64000),
            (const float4*)(g_L + 256000 + b * 800), g_sctr + 256000 + b * 800, start, 64000, p); break;
    case 3: collect_body<208>((const float4*)(P.cls[3] + (size_t)b * 16640),
            (const float4*)(g_L + 268800 + b * 208), g_sctr + 268800 + b * 208, start, 16640, p); break;
    case 4: collect_body<56>((const float4*)(P.cls[4] + (size_t)b * 4480),
            (const float4*)(g_L + 272128 + b * 56), g_sctr + 272128 + b * 56, start, 4480, p); break;
    }
}

// monotone 1024-bin key for score-prune (hi in [0x80000000, 0xBF800000])
__device__ __forceinline__ int keybin(unsigned hi) {
    int d = (int)(hi - 0xBD000000u);
    d >>= 16;
    return min(1023, max(d, 0));
}

// ---------------- kernel 4: exact per-pair top-300 [R6/R13-proven] -----------
__global__ __launch_bounds__(512) void k_select(InPtrs P) {
    __shared__ unsigned long long sk[CAP];
    __shared__ unsigned hist[1024];
    __shared__ unsigned part[512];
    __shared__ int s_cnt2;
    __shared__ int s_B;
    int p = blockIdx.x, t = threadIdx.x;
    int l = p / 16, b = p % 16;
    int n = min((int)g_scnt[p], CAP);
    const unsigned long long* sv = g_surv + (size_t)p * CAP;
    int m = n;
    bool pruned = false;
    if (n > 1024) {
        for (int i = t; i < 1024; i += 512) hist[i] = 0;
        if (t == 0) { s_cnt2 = 0; s_B = 0; }
        __syncthreads();
        for (int i = t; i < n; i += 512)
            atomicAdd(&hist[keybin((unsigned)(sv[i] >> 32))], 1u);
        __syncthreads();
        unsigned lsum = hist[2 * t] + hist[2 * t + 1];
        part[t] = lsum;
        __syncthreads();
        for (int off = 1; off < 512; off <<= 1) {
            unsigned o = (t + off < 512) ? part[t + off] : 0u;
            __syncthreads();
            part[t] += o;
            __syncthreads();
        }
        unsigned cum = (t < 511) ? part[t + 1] : 0u;
        unsigned h1 = hist[2 * t + 1], h0 = hist[2 * t];
        if (cum < 300u && cum + h1 >= 300u) s_B = 2 * t + 1;
        cum += h1;
        if (cum < 300u && cum + h0 >= 300u) s_B = 2 * t;
        __syncthreads();
        int B = s_B;
        for (int i = t; i < n; i += 512) {
            unsigned long long key = sv[i];
            if (keybin((unsigned)(key >> 32)) >= B) {
                int idx = atomicAdd(&s_cnt2, 1);
                if (idx < CAP) sk[idx] = key;
            }
        }
        __syncthreads();
        if (s_cnt2 <= 1024) { m = s_cnt2; pruned = true; }
    }
    int P2 = 512; while (P2 < m) P2 <<= 1;
    for (int i = t; i < P2; i += 512) {
        if (i < m) { if (!pruned) sk[i] = sv[i]; }
        else sk[i] = 0ull;
    }
    __syncthreads();
    for (int k2 = 2; k2 <= P2; k2 <<= 1)
        for (int j = k2 >> 1; j > 0; j >>= 1) {
            for (int i = t; i < P2; i += 512) {
                int ix = i ^ j;
                if (ix > i) {
                    bool up = ((i & k2) == 0);
                    unsigned long long a = sk[i], c = sk[ix];
                    if (up ? (a < c) : (a > c)) { sk[i] = c; sk[ix] = a; }
                }
            }
            __syncthreads();
        }
    if (t < TOPN) {
        int ci = b * KC + l * TOPN + t;
        bool valid = false;
        if (t < m) {
            unsigned long long key = sk[t];
            unsigned hi = (unsigned)(key >> 32);
            if (hi > 0x80000000u) {
                valid = true;
                float sc = __uint_as_float(hi ^ 0x80000000u);
                unsigned idx = ~(unsigned)(key & 0xFFFFFFFFu);
                int pos = (int)(idx / NCLS), c = (int)(idx % NCLS);
                int hw = c_HW[l];
                const float* bx = P.box[l] + (size_t)b * 4 * hw;
                float bl = bx[pos], bt = bx[hw + pos], br = bx[2 * hw + pos], bbo = bx[3 * hw + pos];
                float lx = P.loc[l][2 * pos], ly = P.loc[l][2 * pos + 1];
                float x1 = fminf(fmaxf(lx - bl, 0.f), 1023.f);
                float y1 = fminf(fmaxf(ly - bt, 0.f), 799.f);
                float x2 = fminf(fmaxf(lx + br, 0.f), 1023.f);
                float y2 = fminf(fmaxf(ly + bbo, 0.f), 799.f);
                g_cscore[ci] = sqrtf(fmaxf(sc, 1e-12f));
                g_cbox4[ci] = make_float4(x1, y1, x2, y2);
                g_clabel[ci] = c + 1;
            }
        }
        if (!valid) g_cscore[ci] = -1.0f;   // replay-safe sentinel (all 1500 written)
    }
}

// ---------------- kernel 5: sort + chunked mask-based NMS + emit -------------
__global__ __launch_bounds__(1024) void k_final(float* out) {
    __shared__ __align__(16) unsigned char s_raw[24064];   // skey(16KB) | sb(23.5KB)
    __shared__ float sa[KC];
    __shared__ float ssc[KC];
    __shared__ unsigned short sslot[KC];
    __shared__ unsigned svalid[NWORDS];
    __shared__ unsigned ssup[NWORDS];
    __shared__ int slist[POST];
    __shared__ int s_cnt;
    __shared__ unsigned s_kept;
    unsigned long long* skey = (unsigned long long*)s_raw;
    float4* sb = (float4*)s_raw;
    int b = blockIdx.x, t = threadIdx.x;
    if (t < NWORDS) { svalid[t] = 0; ssup[t] = 0; }
    if (t == 0) s_cnt = 0;
    // phase 1: keys (score desc, slot asc via ~slot) + bitonic sort [proven]
    for (int i = t; i < 2048; i += 1024) {
        unsigned long long kk = 0ull;
        if (i < NREAL) {
            float sc = g_cscore[b * KC + i];
            kk = ((unsigned long long)fkey(sc) << 32) | (unsigned)(~(unsigned)i);
        }
        skey[i] = kk;
    }
    for (int k2 = 2; k2 <= 2048; k2 <<= 1)
        for (int j = k2 >> 1; j > 0; j >>= 1) {
            __syncthreads();
            for (int i = t; i < 2048; i += 1024) {
                int ix = i ^ j;
                if (ix > i) {
                    bool up = ((i & k2) == 0);
                    unsigned long long a = skey[i], c = skey[ix];
                    if (up ? (a < c) : (a > c)) { skey[i] = c; skey[ix] = a; }
                }
            }
        }
    __syncthreads();
    // phase 2: decode into sb/sa/ssc/sslot (sb overlays skey)  [proven]
    unsigned long long kkA = skey[t];
    unsigned long long kkB = (t + 1024 < 2048) ? skey[t + 1024] : 0ull;
    __syncthreads();
    #pragma unroll
    for (int half = 0; half < 2; half++) {
        int i = t + half * 1024;
        if (i >= KC) break;
        unsigned long long kk = half ? kkB : kkA;
        unsigned hi = (unsigned)(kk >> 32);
        if (hi > 0x80000000u) {
            int slot = (int)(~(unsigned)(kk & 0xFFFFFFFFu));
            int ci = b * KC + slot;
            float4 bx = g_cbox4[ci];
            float off = (float)g_clabel[ci] * 1025.0f;
            float4 ob = make_float4(bx.x + off, bx.y + off, bx.z + off, bx.w + off);
            sb[i] = ob;
            sa[i] = (ob.z - ob.x) * (ob.w - ob.y);
            ssc[i] = __uint_as_float(hi ^ 0x80000000u);
            sslot[i] = (unsigned short)slot;
            atomicOr(&svalid[i >> 5], 1u << (i & 31));
        } else {
            sb[i] = make_float4(0.f, 0.f, 0.f, 0.f);
            sa[i] = 0.f; ssc[i] = -1e30f; sslot[i] = 0;
        }
    }
    __syncthreads();
    // phase 3: chunked NMS — parallel pairwise masks, ballot-serial resolve
    for (int w = 0; w < NWORDS; w++) {
        if (t < 32) {
            int i = (w << 5) + t;
            float4 bi = sb[i];
            float ai = sa[i];
            // lane t: mask of all j != t in this word with IoU(i,j) > thr
            unsigned supin = 0;
            #pragma unroll 8
            for (int j = 0; j < 32; j++) {
                int k = (w << 5) + j;
                float4 bj = sb[k];              // broadcast LDS
                float iw = fminf(bi.z, bj.z) - fmaxf(bi.x, bj.x);
                float ih = fminf(bi.w, bj.w) - fmaxf(bi.y, bj.y);
                float inter = fmaxf(iw, 0.f) * fmaxf(ih, 0.f);
                float uni = fmaxf(ai + sa[k] - inter, 1e-9f);
                if (inter > 0.6f * uni && j != t) supin |= 1u << j;
            }
            unsigned alive = svalid[w] & ~ssup[w];
            unsigned kept = 0;
            int cnt = s_cnt;
            while (alive && cnt < POST) {
                int bit = __ffs(alive) - 1;
                kept |= 1u << bit;
                if (t == 0) slist[cnt] = (w << 5) + bit;
                cnt++;
                unsigned supnow = __ballot_sync(0xffffffffu, (supin >> bit) & 1u);
                alive &= ~supnow & ~(1u << bit);
            }
            if (t == 0) { s_cnt = cnt; s_kept = kept; }
        }
        __syncthreads();
        int cnt = s_cnt;
        unsigned kept = s_kept;
        bool last = (cnt >= POST) || (w == NWORDS - 1);
        if (kept && !last) {
            // apply this word's kept-set to all later candidates  [R13-proven]
            for (int j = ((w + 1) << 5) + t; j < KC; j += 1024) {
                float4 bj = sb[j];
                float aj = sa[j];
                bool sup = false;
                unsigned kb = kept;
                while (kb) {
                    int bit = __ffs(kb) - 1; kb &= kb - 1;
                    int k = (w << 5) + bit;
                    float4 bk = sb[k];          // broadcast LDS
                    float iw = fminf(bj.z, bk.z) - fmaxf(bj.x, bk.x);
                    float ih = fminf(bj.w, bk.w) - fmaxf(bj.y, bk.y);
                    float inter = fmaxf(iw, 0.f) * fmaxf(ih, 0.f);
                    float uni = fmaxf(aj + sa[k] - inter, 1e-9f);
                    sup |= inter > 0.6f * uni;
                }
                unsigned m = __ballot_sync(0xffffffffu, sup);   // warp = one word
                if ((t & 31) == 0 && m) atomicOr(&ssup[j >> 5], m);
            }
        }
        __syncthreads();
        if (last && cnt >= POST) break;
    }
    __syncthreads();
    // phase 4: emit
    int cnt = s_cnt;
    float* o5 = out + (size_t)b * POST * 5;
    float* ol = out + NBATCH * POST * 5 + b * POST;
    float* ov = out + NBATCH * POST * 5 + NBATCH * POST + b * POST;
    for (int k = t; k < POST; k += 1024) {
        float b0 = 0.f, b1 = 0.f, b2 = 0.f, b3 = 0.f, sc = 0.f, lab = 0.f, val = 0.f;
        if (k < cnt) {
            int i = slist[k];
            int ci = b * KC + (int)sslot[i];
            float4 bx = g_cbox4[ci];
            b0 = bx.x; b1 = bx.y; b2 = bx.z; b3 = bx.w;
            sc = ssc[i];
            lab = (float)g_clabel[ci];
            val = 1.0f;
        }
        o5[k * 5 + 0] = b0; o5[k * 5 + 1] = b1;
        o5[k * 5 + 2] = b2; o5[k * 5 + 3] = b3;
        o5[k * 5 + 4] = sc;
        ol[k] = lab; ov[k] = val;
    }
}

// ---------------- launch ------------------------------------------------------
extern "C" void kernel_launch(void* const* d_in, const int* in_sizes, int n_in,
                              void* d_out, int out_size) {
    InPtrs P;
    bool sig_order = (n_in < 2) || (in_sizes[1] == 6400);
    for (int l = 0; l < 5; l++) {
        if (sig_order) {
            P.loc[l] = (const float*)d_in[l];
            P.cls[l] = (const float*)d_in[5 + l];
            P.box[l] = (const float*)d_in[10 + l];
            P.ctr[l] = (const float*)d_in[15 + l];
        } else {
            P.loc[l] = (const float*)d_in[4 * l + 0];
            P.cls[l] = (const float*)d_in[4 * l + 1];
            P.box[l] = (const float*)d_in[4 * l + 2];
            P.ctr[l] = (const float*)d_in[4 * l + 3];
        }
    }
    k_prep<<<SCTR_BLOCKS + NSAMPLE, 256>>>(P);      // 1: sctr + sampled hist
    k_threshL<<<80, 256>>>();                       // 2: threshold -> logit L
    k_collect<<<NBLOCKS_COLLECT, 256>>>(P);         // 3: R13 sweep
    k_select<<<80, 512>>>(P);                       // 4: R13 top-300
    k_final<<<NBATCH, 1024>>>((float*)d_out);       // 5: sort + mask-NMS + emit
}

// round 15
// speedup vs baseline: 1.1377x; 1.1377x over previous
#include <cuda_runtime.h>
#include <math.h>
#include <stdint.h>

// ---------------- problem constants (IMG 800x1024, strides 8..128) ----------
#define NBATCH 16
#define NCLS   80
#define TOPN   300
#define KC     1504          // padded candidates per image (5*300 = 1500 real)
#define NWORDS 47            // ceil(1504/32)
#define POST   100
#define CAP    4096          // survivor cap per (level,batch) pair

__constant__ int c_HW[5]   = {12800, 3200, 800, 208, 56};
__constant__ int c_CHW[5]  = {1024000, 256000, 64000, 16640, 4480};
__constant__ int c_LOFF[5] = {0, 204800, 256000, 268800, 272128};
__constant__ int c_R[5]    = {40, 80, 300, 300, 300};
__constant__ int c_BPP[5]  = {250, 63, 16, 5, 2};
__constant__ int c_BOFF[5] = {0, 4000, 5008, 5264, 5344};
#define NBLOCKS_COLLECT 5376
#define SCTR_TOTAL 273024

// ---------------- device scratch (static, allocation-free) ------------------
__device__ float    g_sctr[SCTR_TOTAL];      // exact sigmoid(ctr)
__device__ float    g_L[SCTR_TOTAL];         // per-position logit threshold
__device__ unsigned g_hist1[80 * 2048];
__device__ unsigned g_scnt[80];
__device__ unsigned long long g_surv[(size_t)80 * CAP];
__device__ float    g_cscore[NBATCH * KC];
__device__ float4   g_cbox4[NBATCH * KC];
__device__ int      g_clabel[NBATCH * KC];

struct InPtrs {
    const float* loc[5];
    const float* cls[5];
    const float* box[5];
    const float* ctr[5];
};

__device__ __forceinline__ unsigned fkey(float f) {
    unsigned b = __float_as_uint(f);
    return b ^ ((unsigned)((int)b >> 31) | 0x80000000u);
}
__device__ __forceinline__ float sigm(float x) { return 1.0f / (1.0f + expf(-x)); }

__device__ __forceinline__ float approx_rcp(float d) {
    float r = __int_as_float(0x7EF311C3 - __float_as_int(d));
    r = r * (2.0f - d * r);
    r = r * (2.0f - d * r);
    return r;
}
// MUFU-free approx sigmoid (sampling only), |rel err| <= ~0.25%
__device__ __forceinline__ float approx_a(float cv, float sv) {
    float t = fminf(cv, 60.0f) * -1.44269504f;
    float fl = floorf(t);
    float f = t - fl;
    float p2 = fmaf(fmaf(0.33718944f, f, 0.65763628f), f, 1.0017247f);
    float z = p2 * __int_as_float(((int)fl + 127) << 23);
    return approx_rcp(1.0f + z) * sv;
}

__device__ __forceinline__ void map_block(int bid, int& l, int& b, int& chunk) {
    if (bid < 4000)      l = 0;
    else if (bid < 5008) l = 1;
    else if (bid < 5264) l = 2;
    else if (bid < 5344) l = 3;
    else                 l = 4;
    int rel = bid - c_BOFF[l];
    b = rel / c_BPP[l];
    chunk = rel % c_BPP[l];
}

// ---------------- kernel 1: zero scratch + exact sigmoid(ctr) [R13-proven] ---
__global__ __launch_bounds__(256) void k_init(InPtrs P) {
    int i = blockIdx.x * 256 + threadIdx.x;
    if (i < 80 * 2048) g_hist1[i] = 0;
    if (i < 80) g_scnt[i] = 0;
    if (i < NBATCH * KC) g_cscore[i] = -1.0f;
    if (i < SCTR_TOTAL) {
        int l = (i < 204800) ? 0 : (i < 256000) ? 1 : (i < 268800) ? 2 : (i < 272128) ? 3 : 4;
        g_sctr[i] = sigm(P.ctr[l][i - c_LOFF[l]]);
    }
}

// ---------------- kernel 2: sampled approx-score histogram [R13-proven] ------
__global__ __launch_bounds__(256) void k_sample(InPtrs P) {
    __shared__ unsigned hist[2048];
    for (int i = threadIdx.x; i < 2048; i += 256) hist[i] = 0;
    __syncthreads();
    int bid = blockIdx.x;
    int l, b, sub, nsub, stride;
    if (bid < 128)      { l = 0; b = bid >> 3; sub = bid & 7; nsub = 8; stride = 32; }
    else if (bid < 160) { l = 1; b = (bid - 128) >> 1; sub = (bid - 128) & 1; nsub = 2; stride = 8; }
    else if (bid < 176) { l = 2; b = bid - 160; sub = 0; nsub = 1; stride = 1; }
    else if (bid < 192) { l = 3; b = bid - 176; sub = 0; nsub = 1; stride = 1; }
    else                { l = 4; b = bid - 192; sub = 0; nsub = 1; stride = 1; }
    int chw4 = c_CHW[l] >> 2;
    int per = chw4 / nsub;
    int hw = c_HW[l];
    const float4* cls4 = (const float4*)(P.cls[l]) + (size_t)b * chw4 + (size_t)sub * per;
    const float4* sctr4 = (const float4*)(g_sctr + c_LOFF[l] + b * hw);
    int base_e = sub * per * 4;
    for (int i4 = threadIdx.x * stride; i4 < per; i4 += 256 * stride) {
        float4 v = cls4[i4];
        int e = base_e + (i4 << 2);
        int pos0 = e % hw;
        float4 s4 = sctr4[pos0 >> 2];
        float vv[4] = {v.x, v.y, v.z, v.w};
        float ss[4] = {s4.x, s4.y, s4.z, s4.w};
        #pragma unroll
        for (int k = 0; k < 4; k++) {
            float cv = vv[k];
            if (cv < -2.945f) continue;
            float a = approx_a(cv, ss[k]);
            atomicAdd(&hist[min(2047, (int)(a * 2048.0f))], 1u);
        }
    }
    __syncthreads();
    int p = l * 16 + b;
    for (int i = threadIdx.x; i < 2048; i += 256)
        if (hist[i]) atomicAdd(&g_hist1[p * 2048 + i], hist[i]);
}

// ---------------- kernel 3: threshold -> per-position logit L [R13-proven] ---
__global__ __launch_bounds__(256) void k_threshL() {
    __shared__ unsigned sh[2048];
    __shared__ unsigned part[256];
    __shared__ float s_thr;
    int p = blockIdx.x, t = threadIdx.x;
    if (t == 0) s_thr = 0.0f;
    unsigned R = (unsigned)c_R[p / 16];
    const unsigned* h = g_hist1 + (size_t)p * 2048;
    unsigned lsum = 0;
    for (int i = 0; i < 8; i++) { unsigned v = h[t * 8 + i]; sh[t * 8 + i] = v; lsum += v; }
    part[t] = lsum;
    __syncthreads();
    for (int off = 1; off < 256; off <<= 1) {
        unsigned o = (t + off < 256) ? part[t + off] : 0u;
        __syncthreads();
        part[t] += o;
        __syncthreads();
    }
    unsigned cum = (t < 255) ? part[t + 1] : 0u;
    for (int i = 7; i >= 0; i--) {
        int bidx = t * 8 + i;
        unsigned hv = sh[bidx];
        if (cum < R && cum + hv >= R)
            s_thr = (float)bidx * (1.0f / 2048.0f) * 0.985f;
        cum += hv;
    }
    __syncthreads();
    float thr = s_thr;
    int l = p / 16, b = p % 16;
    int hw = c_HW[l];
    int base = c_LOFF[l] + b * hw;
    for (int i = t; i < hw; i += 256) {
        float sv = g_sctr[base + i];
        float L;
        if (thr <= 0.0f) L = -2.944f;
        else {
            float x = thr / sv;
            if (x >= 1.0f) L = 1e30f;
            else L = fmaxf(logf(x / (1.0f - x)) - 0.02f, -2.944f);
        }
        g_L[base + i] = L;
    }
}

// ---------------- kernel 4: full sweep [R13-proven float4 body] --------------
template <int HW>
__device__ __forceinline__ void collect_body(const float4* cls4, const float4* Lv,
                                             const float* sctr, int start, int chw, int p) {
    int e4end = min(start + 4096, chw) >> 2;
    for (int e4 = (start >> 2) + threadIdx.x; e4 < e4end; e4 += 256) {
        float4 v = cls4[e4];
        int e = e4 << 2;
        int c0 = e / HW;
        int pos0 = e - c0 * HW;
        float4 L4 = Lv[pos0 >> 2];
        float vv[4] = {v.x, v.y, v.z, v.w};
        float LL[4] = {L4.x, L4.y, L4.z, L4.w};
        #pragma unroll
        for (int k = 0; k < 4; k++) {
            float cv = vv[k];
            if (cv < LL[k]) continue;
            float se = sigm(cv);              // exact path, rare
            if (se <= 0.05f) continue;
            float sv = sctr[pos0 + k];
            float m = se * sv;
            unsigned key32 = __float_as_uint(m) | 0x80000000u;
            unsigned idx = (unsigned)((pos0 + k) * NCLS + c0);
            unsigned long long key = ((unsigned long long)key32 << 32) | (unsigned)(~idx);
            unsigned slot = atomicAdd(&g_scnt[p], 1u);
            if (slot < CAP) g_surv[(size_t)p * CAP + slot] = key;
        }
    }
}

__global__ __launch_bounds__(256) void k_collect(InPtrs P) {
    int l, b, chunk; map_block(blockIdx.x, l, b, chunk);
    int p = l * 16 + b;
    int start = chunk * 4096;
    switch (l) {
    case 0: collect_body<12800>((const float4*)(P.cls[0] + (size_t)b * 1024000),
            (const float4*)(g_L + 0 + b * 12800), g_sctr + 0 + b * 12800, start, 1024000, p); break;
    case 1: collect_body<3200>((const float4*)(P.cls[1] + (size_t)b * 256000),
            (const float4*)(g_L + 204800 + b * 3200), g_sctr + 204800 + b * 3200, start, 256000, p); break;
    case 2: collect_body<800>((const float4*)(P.cls[2] + (size_t)b * 64000),
            (const float4*)(g_L + 256000 + b * 800), g_sctr + 256000 + b * 800, start, 64000, p); break;
    case 3: collect_body<208>((const float4*)(P.cls[3] + (size_t)b * 16640),
            (const float4*)(g_L + 268800 + b * 208), g_sctr + 268800 + b * 208, start, 16640, p); break;
    case 4: collect_body<56>((const float4*)(P.cls[4] + (size_t)b * 4480),
            (const float4*)(g_L + 272128 + b * 56), g_sctr + 272128 + b * 56, start, 4480, p); break;
    }
}

// monotone 1024-bin key for score-prune (hi in [0x80000000, 0xBF800000])
__device__ __forceinline__ int keybin(unsigned hi) {
    int d = (int)(hi - 0xBD000000u);
    d >>= 16;
    return min(1023, max(d, 0));
}

// ---------------- kernel 5: exact per-pair top-300 [R13-proven] --------------
__global__ __launch_bounds__(512) void k_select(InPtrs P) {
    __shared__ unsigned long long sk[CAP];
    __shared__ unsigned hist[1024];
    __shared__ unsigned part[512];
    __shared__ int s_cnt2;
    __shared__ int s_B;
    int p = blockIdx.x, t = threadIdx.x;
    int l = p / 16, b = p % 16;
    int n = min((int)g_scnt[p], CAP);
    const unsigned long long* sv = g_surv + (size_t)p * CAP;
    int m = n;
    bool pruned = false;
    if (n > 1024) {
        for (int i = t; i < 1024; i += 512) hist[i] = 0;
        if (t == 0) { s_cnt2 = 0; s_B = 0; }
        __syncthreads();
        for (int i = t; i < n; i += 512)
            atomicAdd(&hist[keybin((unsigned)(sv[i] >> 32))], 1u);
        __syncthreads();
        unsigned lsum = hist[2 * t] + hist[2 * t + 1];
        part[t] = lsum;
        __syncthreads();
        for (int off = 1; off < 512; off <<= 1) {
            unsigned o = (t + off < 512) ? part[t + off] : 0u;
            __syncthreads();
            part[t] += o;
            __syncthreads();
        }
        unsigned cum = (t < 511) ? part[t + 1] : 0u;
        unsigned h1 = hist[2 * t + 1], h0 = hist[2 * t];
        if (cum < 300u && cum + h1 >= 300u) s_B = 2 * t + 1;
        cum += h1;
        if (cum < 300u && cum + h0 >= 300u) s_B = 2 * t;
        __syncthreads();
        int B = s_B;
        for (int i = t; i < n; i += 512) {
            unsigned long long key = sv[i];
            if (keybin((unsigned)(key >> 32)) >= B) {
                int idx = atomicAdd(&s_cnt2, 1);
                if (idx < CAP) sk[idx] = key;
            }
        }
        __syncthreads();
        if (s_cnt2 <= 1024) { m = s_cnt2; pruned = true; }
    }
    int P2 = 512; while (P2 < m) P2 <<= 1;
    for (int i = t; i < P2; i += 512) {
        if (i < m) { if (!pruned) sk[i] = sv[i]; }
        else sk[i] = 0ull;
    }
    __syncthreads();
    for (int k2 = 2; k2 <= P2; k2 <<= 1)
        for (int j = k2 >> 1; j > 0; j >>= 1) {
            for (int i = t; i < P2; i += 512) {
                int ix = i ^ j;
                if (ix > i) {
                    bool up = ((i & k2) == 0);
                    unsigned long long a = sk[i], c = sk[ix];
                    if (up ? (a < c) : (a > c)) { sk[i] = c; sk[ix] = a; }
                }
            }
            __syncthreads();
        }
    if (t < TOPN) {
        int ci = b * KC + l * TOPN + t;
        bool valid = false;
        if (t < m) {
            unsigned long long key = sk[t];
            unsigned hi = (unsigned)(key >> 32);
            if (hi > 0x80000000u) {
                valid = true;
                float sc = __uint_as_float(hi ^ 0x80000000u);
                unsigned idx = ~(unsigned)(key & 0xFFFFFFFFu);
                int pos = (int)(idx / NCLS), c = (int)(idx % NCLS);
                int hw = c_HW[l];
                const float* bx = P.box[l] + (size_t)b * 4 * hw;
                float bl = bx[pos], bt = bx[hw + pos], br = bx[2 * hw + pos], bbo = bx[3 * hw + pos];
                float lx = P.loc[l][2 * pos], ly = P.loc[l][2 * pos + 1];
                float x1 = fminf(fmaxf(lx - bl, 0.f), 1023.f);
                float y1 = fminf(fmaxf(ly - bt, 0.f), 799.f);
                float x2 = fminf(fmaxf(lx + br, 0.f), 1023.f);
                float y2 = fminf(fmaxf(ly + bbo, 0.f), 799.f);
                g_cscore[ci] = sqrtf(fmaxf(sc, 1e-12f));
                g_cbox4[ci] = make_float4(x1, y1, x2, y2);
                g_clabel[ci] = c + 1;
            }
        }
        if (!valid) g_cscore[ci] = -1.0f;   // replay-safe sentinel
    }
}

// ---------------- kernel 6: sort + LAZY warp-NMS + emit ----------------------
__global__ __launch_bounds__(1024) void k_final(float* out) {
    __shared__ __align__(16) unsigned char s_raw[24064];   // skey(16KB) | sb(23.5KB)
    __shared__ float sa[KC];
    __shared__ float ssc[KC];
    __shared__ unsigned short sslot[KC];
    __shared__ int slist[POST];
    __shared__ int s_cnt;
    unsigned long long* skey = (unsigned long long*)s_raw;
    float4* sb = (float4*)s_raw;
    int b = blockIdx.x, t = threadIdx.x;
    // phase 1: keys (score desc, slot asc via ~slot) + bitonic sort [R13-proven]
    for (int i = t; i < 2048; i += 1024) {
        unsigned long long kk = 0ull;
        if (i < KC) {
            float sc = g_cscore[b * KC + i];
            kk = ((unsigned long long)fkey(sc) << 32) | (unsigned)(~(unsigned)i);
        }
        skey[i] = kk;
    }
    for (int k2 = 2; k2 <= 2048; k2 <<= 1)
        for (int j = k2 >> 1; j > 0; j >>= 1) {
            __syncthreads();
            for (int i = t; i < 2048; i += 1024) {
                int ix = i ^ j;
                if (ix > i) {
                    bool up = ((i & k2) == 0);
                    unsigned long long a = skey[i], c = skey[ix];
                    if (up ? (a < c) : (a > c)) { skey[i] = c; skey[ix] = a; }
                }
            }
        }
    __syncthreads();
    // phase 2: decode into sb/sa/ssc/sslot (sb overlays skey)  [R13-proven]
    unsigned long long kkA = skey[t];
    unsigned long long kkB = (t + 1024 < 2048) ? skey[t + 1024] : 0ull;
    __syncthreads();
    #pragma unroll
    for (int half = 0; half < 2; half++) {
        int i = t + half * 1024;
        if (i >= KC) break;
        unsigned long long kk = half ? kkB : kkA;
        unsigned hi = (unsigned)(kk >> 32);
        if (hi > 0x80000000u) {
            int slot = (int)(~(unsigned)(kk & 0xFFFFFFFFu));
            int ci = b * KC + slot;
            float4 bx = g_cbox4[ci];
            float off = (float)g_clabel[ci] * 1025.0f;
            float4 ob = make_float4(bx.x + off, bx.y + off, bx.z + off, bx.w + off);
            sb[i] = ob;
            sa[i] = (ob.z - ob.x) * (ob.w - ob.y);
            ssc[i] = __uint_as_float(hi ^ 0x80000000u);
            sslot[i] = (unsigned short)slot;
        } else {
            sb[i] = make_float4(0.f, 0.f, 0.f, 0.f);
            sa[i] = 0.f; ssc[i] = -1e30f; sslot[i] = 0;
        }
    }
    __syncthreads();
    // phase 3: LAZY greedy NMS — warp 0 only, no block-wide apply, no atomics
    if (t < 32) {
        int cnt = 0;
        for (int w = 0; w < NWORDS && cnt < POST; w++) {
            int i = (w << 5) + t;
            float4 bi = sb[i];
            float ai = sa[i];
            bool valid = ssc[i] > -1e29f;
            // (a) suppression by already-kept boxes from earlier words
            bool sup = false;
            for (int k = 0; k < cnt; k++) {
                int kk = slist[k];
                float4 bk = sb[kk];             // broadcast LDS
                float iw = fminf(bi.z, bk.z) - fmaxf(bi.x, bk.x);
                float ih = fminf(bi.w, bk.w) - fmaxf(bi.y, bk.y);
                float inter = fmaxf(iw, 0.f) * fmaxf(ih, 0.f);
                float uni = fmaxf(ai + sa[kk] - inter, 1e-9f);
                sup |= inter > 0.6f * uni;
            }
            // (b) within-word pairwise suppression mask (parallel, visited words only)
            unsigned supin = 0;
            #pragma unroll 8
            for (int j = 0; j < 32; j++) {
                int kk = (w << 5) + j;
                float4 bj = sb[kk];             // broadcast LDS
                float iw = fminf(bi.z, bj.z) - fmaxf(bi.x, bj.x);
                float ih = fminf(bi.w, bj.w) - fmaxf(bi.y, bj.y);
                float inter = fmaxf(iw, 0.f) * fmaxf(ih, 0.f);
                float uni = fmaxf(ai + sa[kk] - inter, 1e-9f);
                if (inter > 0.6f * uni && j != t) supin |= 1u << j;
            }
            // (c) ballot-serial greedy resolve within the word
            unsigned alive = __ballot_sync(0xffffffffu, valid && !sup);
            while (alive && cnt < POST) {
                int bit = __ffs(alive) - 1;
                slist[cnt] = (w << 5) + bit;    // all lanes write same value
                cnt++;
                unsigned supnow = __ballot_sync(0xffffffffu, (supin >> bit) & 1u);
                alive &= ~supnow & ~(1u << bit);
            }
        }
        if (t == 0) s_cnt = cnt;
    }
    __syncthreads();
    // phase 4: emit
    int cnt = s_cnt;
    float* o5 = out + (size_t)b * POST * 5;
    float* ol = out + NBATCH * POST * 5 + b * POST;
    float* ov = out + NBATCH * POST * 5 + NBATCH * POST + b * POST;
    for (int k = t; k < POST; k += 1024) {
        float b0 = 0.f, b1 = 0.f, b2 = 0.f, b3 = 0.f, sc = 0.f, lab = 0.f, val = 0.f;
        if (k < cnt) {
            int i = slist[k];
            int ci = b * KC + (int)sslot[i];
            float4 bx = g_cbox4[ci];
            b0 = bx.x; b1 = bx.y; b2 = bx.z; b3 = bx.w;
            sc = ssc[i];
            lab = (float)g_clabel[ci];
            val = 1.0f;
        }
        o5[k * 5 + 0] = b0; o5[k * 5 + 1] = b1;
        o5[k * 5 + 2] = b2; o5[k * 5 + 3] = b3;
        o5[k * 5 + 4] = sc;
        ol[k] = lab; ov[k] = val;
    }
}

// ---------------- launch ------------------------------------------------------
extern "C" void kernel_launch(void* const* d_in, const int* in_sizes, int n_in,
                              void* d_out, int out_size) {
    InPtrs P;
    bool sig_order = (n_in < 2) || (in_sizes[1] == 6400);
    for (int l = 0; l < 5; l++) {
        if (sig_order) {
            P.loc[l] = (const float*)d_in[l];
            P.cls[l] = (const float*)d_in[5 + l];
            P.box[l] = (const float*)d_in[10 + l];
            P.ctr[l] = (const float*)d_in[15 + l];
        } else {
            P.loc[l] = (const float*)d_in[4 * l + 0];
            P.cls[l] = (const float*)d_in[4 * l + 1];
            P.box[l] = (const float*)d_in[4 * l + 2];
            P.ctr[l] = (const float*)d_in[4 * l + 3];
        }
    }
    k_init<<<(SCTR_TOTAL + 255) / 256, 256>>>(P);   // 1: zero + sctr
    k_sample<<<208, 256>>>(P);                      // 2: sampled hist
    k_threshL<<<80, 256>>>();                       // 3: threshold -> logit L
    k_collect<<<NBLOCKS_COLLECT, 256>>>(P);         // 4: R13 sweep
    k_select<<<80, 512>>>(P);                       // 5: R13 top-300
    k_final<<<NBATCH, 1024>>>((float*)d_out);       // 6: sort + lazy NMS + emit
}

// round 16
// speedup vs baseline: 1.2355x; 1.0860x over previous
#include <cuda_runtime.h>
#include <math.h>
#include <stdint.h>

// ---------------- problem constants (IMG 800x1024, strides 8..128) ----------
#define NBATCH 16
#define NCLS   80
#define TOPN   300
#define KC     1504          // padded candidates per image (5*300 = 1500 real)
#define NREAL  1500
#define NWORDS 47            // ceil(1504/32)
#define POST   100
#define CAP    4096          // survivor cap per (level,batch) pair

__constant__ int c_HW[5]   = {12800, 3200, 800, 208, 56};
__constant__ int c_CHW[5]  = {1024000, 256000, 64000, 16640, 4480};
__constant__ int c_LOFF[5] = {0, 204800, 256000, 268800, 272128};
__constant__ int c_R[5]    = {40, 80, 300, 300, 300};
__constant__ int c_BPP[5]  = {250, 63, 16, 5, 2};
__constant__ int c_BOFF[5] = {0, 4000, 5008, 5264, 5344};
#define NBLOCKS_COLLECT 5376
#define SCTR_TOTAL 273024

// ---------------- device scratch (static, allocation-free) ------------------
__device__ float    g_sctr[SCTR_TOTAL];      // exact sigmoid(ctr)
__device__ float    g_L[SCTR_TOTAL];         // per-position logit threshold
__device__ unsigned g_hist1[80 * 2048];
__device__ unsigned g_scnt[80];
__device__ unsigned long long g_surv[(size_t)80 * CAP];
__device__ float    g_cscore[NBATCH * KC];
__device__ float4   g_cbox4[NBATCH * KC];
__device__ int      g_clabel[NBATCH * KC];

struct InPtrs {
    const float* loc[5];
    const float* cls[5];
    const float* box[5];
    const float* ctr[5];
};

__device__ __forceinline__ unsigned fkey(float f) {
    unsigned b = __float_as_uint(f);
    return b ^ ((unsigned)((int)b >> 31) | 0x80000000u);
}
__device__ __forceinline__ float sigm(float x) { return 1.0f / (1.0f + expf(-x)); }

__device__ __forceinline__ float approx_rcp(float d) {
    float r = __int_as_float(0x7EF311C3 - __float_as_int(d));
    r = r * (2.0f - d * r);
    r = r * (2.0f - d * r);
    return r;
}
// MUFU-free approx sigmoid (sampling only), |rel err| <= ~0.25%
__device__ __forceinline__ float approx_a(float cv, float sv) {
    float t = fminf(cv, 60.0f) * -1.44269504f;
    float fl = floorf(t);
    float f = t - fl;
    float p2 = fmaf(fmaf(0.33718944f, f, 0.65763628f), f, 1.0017247f);
    float z = p2 * __int_as_float(((int)fl + 127) << 23);
    return approx_rcp(1.0f + z) * sv;
}

__device__ __forceinline__ void map_block(int bid, int& l, int& b, int& chunk) {
    if (bid < 4000)      l = 0;
    else if (bid < 5008) l = 1;
    else if (bid < 5264) l = 2;
    else if (bid < 5344) l = 3;
    else                 l = 4;
    int rel = bid - c_BOFF[l];
    b = rel / c_BPP[l];
    chunk = rel % c_BPP[l];
}

// ---------------- kernel 1: zero scratch + exact sigmoid(ctr) [R15-proven] ---
__global__ __launch_bounds__(256) void k_init(InPtrs P) {
    int i = blockIdx.x * 256 + threadIdx.x;
    if (i < 80 * 2048) g_hist1[i] = 0;
    if (i < 80) g_scnt[i] = 0;
    if (i < NBATCH * KC) g_cscore[i] = -1.0f;
    if (i < SCTR_TOTAL) {
        int l = (i < 204800) ? 0 : (i < 256000) ? 1 : (i < 268800) ? 2 : (i < 272128) ? 3 : 4;
        g_sctr[i] = sigm(P.ctr[l][i - c_LOFF[l]]);
    }
}

// ---------------- kernel 2: sampled approx-score histogram [R15-proven] ------
__global__ __launch_bounds__(256) void k_sample(InPtrs P) {
    __shared__ unsigned hist[2048];
    for (int i = threadIdx.x; i < 2048; i += 256) hist[i] = 0;
    __syncthreads();
    int bid = blockIdx.x;
    int l, b, sub, nsub, stride;
    if (bid < 128)      { l = 0; b = bid >> 3; sub = bid & 7; nsub = 8; stride = 32; }
    else if (bid < 160) { l = 1; b = (bid - 128) >> 1; sub = (bid - 128) & 1; nsub = 2; stride = 8; }
    else if (bid < 176) { l = 2; b = bid - 160; sub = 0; nsub = 1; stride = 1; }
    else if (bid < 192) { l = 3; b = bid - 176; sub = 0; nsub = 1; stride = 1; }
    else                { l = 4; b = bid - 192; sub = 0; nsub = 1; stride = 1; }
    int chw4 = c_CHW[l] >> 2;
    int per = chw4 / nsub;
    int hw = c_HW[l];
    const float4* cls4 = (const float4*)(P.cls[l]) + (size_t)b * chw4 + (size_t)sub * per;
    const float4* sctr4 = (const float4*)(g_sctr + c_LOFF[l] + b * hw);
    int base_e = sub * per * 4;
    for (int i4 = threadIdx.x * stride; i4 < per; i4 += 256 * stride) {
        float4 v = cls4[i4];
        int e = base_e + (i4 << 2);
        int pos0 = e % hw;
        float4 s4 = sctr4[pos0 >> 2];
        float vv[4] = {v.x, v.y, v.z, v.w};
        float ss[4] = {s4.x, s4.y, s4.z, s4.w};
        #pragma unroll
        for (int k = 0; k < 4; k++) {
            float cv = vv[k];
            if (cv < -2.945f) continue;
            float a = approx_a(cv, ss[k]);
            atomicAdd(&hist[min(2047, (int)(a * 2048.0f))], 1u);
        }
    }
    __syncthreads();
    int p = l * 16 + b;
    for (int i = threadIdx.x; i < 2048; i += 256)
        if (hist[i]) atomicAdd(&g_hist1[p * 2048 + i], hist[i]);
}

// ---------------- kernel 3: threshold -> per-position logit L [R15-proven] ---
__global__ __launch_bounds__(256) void k_threshL() {
    __shared__ unsigned sh[2048];
    __shared__ unsigned part[256];
    __shared__ float s_thr;
    int p = blockIdx.x, t = threadIdx.x;
    if (t == 0) s_thr = 0.0f;
    unsigned R = (unsigned)c_R[p / 16];
    const unsigned* h = g_hist1 + (size_t)p * 2048;
    unsigned lsum = 0;
    for (int i = 0; i < 8; i++) { unsigned v = h[t * 8 + i]; sh[t * 8 + i] = v; lsum += v; }
    part[t] = lsum;
    __syncthreads();
    for (int off = 1; off < 256; off <<= 1) {
        unsigned o = (t + off < 256) ? part[t + off] : 0u;
        __syncthreads();
        part[t] += o;
        __syncthreads();
    }
    unsigned cum = (t < 255) ? part[t + 1] : 0u;
    for (int i = 7; i >= 0; i--) {
        int bidx = t * 8 + i;
        unsigned hv = sh[bidx];
        if (cum < R && cum + hv >= R)
            s_thr = (float)bidx * (1.0f / 2048.0f) * 0.985f;
        cum += hv;
    }
    __syncthreads();
    float thr = s_thr;
    int l = p / 16, b = p % 16;
    int hw = c_HW[l];
    int base = c_LOFF[l] + b * hw;
    for (int i = t; i < hw; i += 256) {
        float sv = g_sctr[base + i];
        float L;
        if (thr <= 0.0f) L = -2.944f;
        else {
            float x = thr / sv;
            if (x >= 1.0f) L = 1e30f;
            else L = fmaxf(logf(x / (1.0f - x)) - 0.02f, -2.944f);
        }
        g_L[base + i] = L;
    }
}

// ---------------- kernel 4: full sweep [R15-proven float4 body] --------------
template <int HW>
__device__ __forceinline__ void collect_body(const float4* cls4, const float4* Lv,
                                             const float* sctr, int start, int chw, int p) {
    int e4end = min(start + 4096, chw) >> 2;
    for (int e4 = (start >> 2) + threadIdx.x; e4 < e4end; e4 += 256) {
        float4 v = cls4[e4];
        int e = e4 << 2;
        int c0 = e / HW;
        int pos0 = e - c0 * HW;
        float4 L4 = Lv[pos0 >> 2];
        float vv[4] = {v.x, v.y, v.z, v.w};
        float LL[4] = {L4.x, L4.y, L4.z, L4.w};
        #pragma unroll
        for (int k = 0; k < 4; k++) {
            float cv = vv[k];
            if (cv < LL[k]) continue;
            float se = sigm(cv);              // exact path, rare
            if (se <= 0.05f) continue;
            float sv = sctr[pos0 + k];
            float m = se * sv;
            unsigned key32 = __float_as_uint(m) | 0x80000000u;
            unsigned idx = (unsigned)((pos0 + k) * NCLS + c0);
            unsigned long long key = ((unsigned long long)key32 << 32) | (unsigned)(~idx);
            unsigned slot = atomicAdd(&g_scnt[p], 1u);
            if (slot < CAP) g_surv[(size_t)p * CAP + slot] = key;
        }
    }
}

__global__ __launch_bounds__(256) void k_collect(InPtrs P) {
    int l, b, chunk; map_block(blockIdx.x, l, b, chunk);
    int p = l * 16 + b;
    int start = chunk * 4096;
    switch (l) {
    case 0: collect_body<12800>((const float4*)(P.cls[0] + (size_t)b * 1024000),
            (const float4*)(g_L + 0 + b * 12800), g_sctr + 0 + b * 12800, start, 1024000, p); break;
    case 1: collect_body<3200>((const float4*)(P.cls[1] + (size_t)b * 256000),
            (const float4*)(g_L + 204800 + b * 3200), g_sctr + 204800 + b * 3200, start, 256000, p); break;
    case 2: collect_body<800>((const float4*)(P.cls[2] + (size_t)b * 64000),
            (const float4*)(g_L + 256000 + b * 800), g_sctr + 256000 + b * 800, start, 64000, p); break;
    case 3: collect_body<208>((const float4*)(P.cls[3] + (size_t)b * 16640),
            (const float4*)(g_L + 268800 + b * 208), g_sctr + 268800 + b * 208, start, 16640, p); break;
    case 4: collect_body<56>((const float4*)(P.cls[4] + (size_t)b * 4480),
            (const float4*)(g_L + 272128 + b * 56), g_sctr + 272128 + b * 56, start, 4480, p); break;
    }
}

// monotone 1024-bin key for score-prune (hi in [0x80000000, 0xBF800000])
__device__ __forceinline__ int keybin(unsigned hi) {
    int d = (int)(hi - 0xBD000000u);
    d >>= 16;
    return min(1023, max(d, 0));
}

// ---------------- kernel 5: exact per-pair top-300 [R15-proven] --------------
__global__ __launch_bounds__(512) void k_select(InPtrs P) {
    __shared__ unsigned long long sk[CAP];
    __shared__ unsigned hist[1024];
    __shared__ unsigned part[512];
    __shared__ int s_cnt2;
    __shared__ int s_B;
    int p = blockIdx.x, t = threadIdx.x;
    int l = p / 16, b = p % 16;
    int n = min((int)g_scnt[p], CAP);
    const unsigned long long* sv = g_surv + (size_t)p * CAP;
    int m = n;
    bool pruned = false;
    if (n > 1024) {
        for (int i = t; i < 1024; i += 512) hist[i] = 0;
        if (t == 0) { s_cnt2 = 0; s_B = 0; }
        __syncthreads();
        for (int i = t; i < n; i += 512)
            atomicAdd(&hist[keybin((unsigned)(sv[i] >> 32))], 1u);
        __syncthreads();
        unsigned lsum = hist[2 * t] + hist[2 * t + 1];
        part[t] = lsum;
        __syncthreads();
        for (int off = 1; off < 512; off <<= 1) {
            unsigned o = (t + off < 512) ? part[t + off] : 0u;
            __syncthreads();
            part[t] += o;
            __syncthreads();
        }
        unsigned cum = (t < 511) ? part[t + 1] : 0u;
        unsigned h1 = hist[2 * t + 1], h0 = hist[2 * t];
        if (cum < 300u && cum + h1 >= 300u) s_B = 2 * t + 1;
        cum += h1;
        if (cum < 300u && cum + h0 >= 300u) s_B = 2 * t;
        __syncthreads();
        int B = s_B;
        for (int i = t; i < n; i += 512) {
            unsigned long long key = sv[i];
            if (keybin((unsigned)(key >> 32)) >= B) {
                int idx = atomicAdd(&s_cnt2, 1);
                if (idx < CAP) sk[idx] = key;
            }
        }
        __syncthreads();
        if (s_cnt2 <= 1024) { m = s_cnt2; pruned = true; }
    }
    int P2 = 512; while (P2 < m) P2 <<= 1;
    for (int i = t; i < P2; i += 512) {
        if (i < m) { if (!pruned) sk[i] = sv[i]; }
        else sk[i] = 0ull;
    }
    __syncthreads();
    for (int k2 = 2; k2 <= P2; k2 <<= 1)
        for (int j = k2 >> 1; j > 0; j >>= 1) {
            for (int i = t; i < P2; i += 512) {
                int ix = i ^ j;
                if (ix > i) {
                    bool up = ((i & k2) == 0);
                    unsigned long long a = sk[i], c = sk[ix];
                    if (up ? (a < c) : (a > c)) { sk[i] = c; sk[ix] = a; }
                }
            }
            __syncthreads();
        }
    if (t < TOPN) {
        int ci = b * KC + l * TOPN + t;
        bool valid = false;
        if (t < m) {
            unsigned long long key = sk[t];
            unsigned hi = (unsigned)(key >> 32);
            if (hi > 0x80000000u) {
                valid = true;
                float sc = __uint_as_float(hi ^ 0x80000000u);
                unsigned idx = ~(unsigned)(key & 0xFFFFFFFFu);
                int pos = (int)(idx / NCLS), c = (int)(idx % NCLS);
                int hw = c_HW[l];
                const float* bx = P.box[l] + (size_t)b * 4 * hw;
                float bl = bx[pos], bt = bx[hw + pos], br = bx[2 * hw + pos], bbo = bx[3 * hw + pos];
                float lx = P.loc[l][2 * pos], ly = P.loc[l][2 * pos + 1];
                float x1 = fminf(fmaxf(lx - bl, 0.f), 1023.f);
                float y1 = fminf(fmaxf(ly - bt, 0.f), 799.f);
                float x2 = fminf(fmaxf(lx + br, 0.f), 1023.f);
                float y2 = fminf(fmaxf(ly + bbo, 0.f), 799.f);
                g_cscore[ci] = sqrtf(fmaxf(sc, 1e-12f));
                g_cbox4[ci] = make_float4(x1, y1, x2, y2);
                g_clabel[ci] = c + 1;
            }
        }
        if (!valid) g_cscore[ci] = -1.0f;   // replay-safe sentinel (all 1500 written)
    }
}

// ---------------- kernel 6: merge-rank + lazy warp-NMS + emit ----------------
// Each level block of 300 slots is already sorted desc by (score ‖ ~slot)
// (select's bitonic key order + slot layout). Global rank via 5 binary searches.
__global__ __launch_bounds__(1024) void k_final(float* out) {
    __shared__ __align__(16) unsigned char s_raw[24064];   // skey(12KB) | sb(23.5KB)
    __shared__ unsigned short ssort[NREAL];
    __shared__ float sa[KC];
    __shared__ float ssc[KC];
    __shared__ unsigned short sslot[KC];
    __shared__ int slist[POST];
    __shared__ int s_cnt;
    unsigned long long* skey = (unsigned long long*)s_raw;  // [NREAL]
    float4* sb = (float4*)s_raw;                            // overlays after ranking
    int b = blockIdx.x, t = threadIdx.x;
    // phase 1a: build keys (global order: score desc, slot asc via ~slot)
    for (int i = t; i < NREAL; i += 1024) {
        float sc = g_cscore[b * KC + i];
        skey[i] = ((unsigned long long)fkey(sc) << 32) | (unsigned)(~(unsigned)i);
    }
    __syncthreads();
    // phase 1b: rank = sum over 5 descending blocks of count(key > mine)
    #pragma unroll
    for (int half = 0; half < 2; half++) {
        int i = t + half * 1024;
        if (i >= NREAL) break;
        unsigned long long x = skey[i];
        int rank = 0;
        #pragma unroll
        for (int m = 0; m < 5; m++) {
            const unsigned long long* arr = skey + m * TOPN;
            int lo = 0, hi = TOPN;
            while (lo < hi) {
                int mid = (lo + hi) >> 1;
                if (arr[mid] > x) lo = mid + 1; else hi = mid;
            }
            rank += lo;
        }
        ssort[rank] = (unsigned short)i;     // permutation: no conflicts
    }
    __syncthreads();
    // phase 2: decode by rank into sb/sa/ssc/sslot (sb overlays skey)
    #pragma unroll
    for (int half = 0; half < 2; half++) {
        int j = t + half * 1024;
        if (j >= KC) break;
        bool val = false;
        if (j < NREAL) {
            int i = (int)ssort[j];
            int ci = b * KC + i;
            float sc = g_cscore[ci];
            if (sc > 0.f) {
                float4 bx = g_cbox4[ci];
                float off = (float)g_clabel[ci] * 1025.0f;
                float4 ob = make_float4(bx.x + off, bx.y + off, bx.z + off, bx.w + off);
                sb[j] = ob;
                sa[j] = (ob.z - ob.x) * (ob.w - ob.y);
                ssc[j] = sc;
                sslot[j] = (unsigned short)i;
                val = true;
            }
        }
        if (!val) {
            sb[j] = make_float4(0.f, 0.f, 0.f, 0.f);
            sa[j] = 0.f; ssc[j] = -1e30f; sslot[j] = 0;
        }
    }
    __syncthreads();
    // phase 3: LAZY greedy NMS — warp 0 only [R15-proven]
    if (t < 32) {
        int cnt = 0;
        for (int w = 0; w < NWORDS && cnt < POST; w++) {
            int i = (w << 5) + t;
            float4 bi = sb[i];
            float ai = sa[i];
            bool valid = ssc[i] > -1e29f;
            bool sup = false;
            for (int k = 0; k < cnt; k++) {
                int kk = slist[k];
                float4 bk = sb[kk];             // broadcast LDS
                float iw = fminf(bi.z, bk.z) - fmaxf(bi.x, bk.x);
                float ih = fminf(bi.w, bk.w) - fmaxf(bi.y, bk.y);
                float inter = fmaxf(iw, 0.f) * fmaxf(ih, 0.f);
                float uni = fmaxf(ai + sa[kk] - inter, 1e-9f);
                sup |= inter > 0.6f * uni;
            }
            unsigned supin = 0;
            #pragma unroll 8
            for (int j = 0; j < 32; j++) {
                int kk = (w << 5) + j;
                float4 bj = sb[kk];             // broadcast LDS
                float iw = fminf(bi.z, bj.z) - fmaxf(bi.x, bj.x);
                float ih = fminf(bi.w, bj.w) - fmaxf(bi.y, bj.y);
                float inter = fmaxf(iw, 0.f) * fmaxf(ih, 0.f);
                float uni = fmaxf(ai + sa[kk] - inter, 1e-9f);
                if (inter > 0.6f * uni && j != t) supin |= 1u << j;
            }
            unsigned alive = __ballot_sync(0xffffffffu, valid && !sup);
            while (alive && cnt < POST) {
                int bit = __ffs(alive) - 1;
                slist[cnt] = (w << 5) + bit;
                cnt++;
                unsigned supnow = __ballot_sync(0xffffffffu, (supin >> bit) & 1u);
                alive &= ~supnow & ~(1u << bit);
            }
        }
        if (t == 0) s_cnt = cnt;
    }
    __syncthreads();
    // phase 4: emit
    int cnt = s_cnt;
    float* o5 = out + (size_t)b * POST * 5;
    float* ol = out + NBATCH * POST * 5 + b * POST;
    float* ov = out + NBATCH * POST * 5 + NBATCH * POST + b * POST;
    for (int k = t; k < POST; k += 1024) {
        float b0 = 0.f, b1 = 0.f, b2 = 0.f, b3 = 0.f, sc = 0.f, lab = 0.f, val = 0.f;
        if (k < cnt) {
            int i = slist[k];
            int ci = b * KC + (int)sslot[i];
            float4 bx = g_cbox4[ci];
            b0 = bx.x; b1 = bx.y; b2 = bx.z; b3 = bx.w;
            sc = ssc[i];
            lab = (float)g_clabel[ci];
            val = 1.0f;
        }
        o5[k * 5 + 0] = b0; o5[k * 5 + 1] = b1;
        o5[k * 5 + 2] = b2; o5[k * 5 + 3] = b3;
        o5[k * 5 + 4] = sc;
        ol[k] = lab; ov[k] = val;
    }
}

// ---------------- launch ------------------------------------------------------
extern "C" void kernel_launch(void* const* d_in, const int* in_sizes, int n_in,
                              void* d_out, int out_size) {
    InPtrs P;
    bool sig_order = (n_in < 2) || (in_sizes[1] == 6400);
    for (int l = 0; l < 5; l++) {
        if (sig_order) {
            P.loc[l] = (const float*)d_in[l];
            P.cls[l] = (const float*)d_in[5 + l];
            P.box[l] = (const float*)d_in[10 + l];
            P.ctr[l] = (const float*)d_in[15 + l];
        } else {
            P.loc[l] = (const float*)d_in[4 * l + 0];
            P.cls[l] = (const float*)d_in[4 * l + 1];
            P.box[l] = (const float*)d_in[4 * l + 2];
            P.ctr[l] = (const float*)d_in[4 * l + 3];
        }
    }
    k_init<<<(SCTR_TOTAL + 255) / 256, 256>>>(P);   // 1: zero + sctr
    k_sample<<<208, 256>>>(P);                      // 2: sampled hist
    k_threshL<<<80, 256>>>();                       // 3: threshold -> logit L
    k_collect<<<NBLOCKS_COLLECT, 256>>>(P);         // 4: R15 sweep
    k_select<<<80, 512>>>(P);                       // 5: R15 top-300
    k_final<<<NBATCH, 1024>>>((float*)d_out);       // 6: merge-rank + lazy NMS
}